// round 3
// baseline (speedup 1.0000x reference)
#include <cuda_runtime.h>
#include <math.h>

#define BB 2
#define TT 2048
#define EE 512
#define NHH 8
#define HDD 64
#define BHH (BB*NHH)
#define E3 (3*EE)
#define SCALE_F 0.125f

typedef unsigned long long u64;

// Scratch (no allocations allowed)
__device__ float g_qkv[(size_t)BB * TT * E3];    // 25 MB
__device__ float g_params[(size_t)BHH * TT * 6];
__device__ float g_attn[(size_t)BB * TT * EE];   // 8 MB

// ---------------------------------------------------------------------------
// Packed f32x2 helpers
// ---------------------------------------------------------------------------
__device__ __forceinline__ u64 pack2(float lo, float hi) {
    u64 r; asm("mov.b64 %0, {%1,%2};" : "=l"(r) : "f"(lo), "f"(hi)); return r;
}
__device__ __forceinline__ void unpack2(u64 v, float& lo, float& hi) {
    asm("mov.b64 {%0,%1}, %2;" : "=f"(lo), "=f"(hi) : "l"(v));
}
__device__ __forceinline__ u64 fma2(u64 a, u64 b, u64 c) {
    u64 d; asm("fma.rn.f32x2 %0, %1, %2, %3;" : "=l"(d) : "l"(a), "l"(b), "l"(c)); return d;
}
__device__ __forceinline__ u64 mul2(u64 a, u64 b) {
    u64 d; asm("mul.rn.f32x2 %0, %1, %2;" : "=l"(d) : "l"(a), "l"(b)); return d;
}

// ---------------------------------------------------------------------------
// GEMM: C[M,N] = A[M,K] @ W[K,N] + bias. BM=128, BN=64, BK=16, 256 threads.
// Thread tile 8(M)x4(N) via FFMA2 pairs along N. A stored in smem as
// duplicated u64 pairs, transposed [k][row]. Register-prefetched globals.
// ---------------------------------------------------------------------------
__global__ __launch_bounds__(256) void gemm_bias_kernel(
    const float* __restrict__ A, const float* __restrict__ W,
    const float* __restrict__ bias, float* __restrict__ C,
    int M, int N, int K)
{
    __shared__ __align__(16) u64  Ast2[16 * 130]; // [k][row] dup pairs
    __shared__ __align__(16) float Bs[16 * 68];   // [k][col]

    int bm = blockIdx.y * 128;
    int bn = blockIdx.x * 64;
    int tid = threadIdx.x;
    int tx = tid & 15, ty = tid >> 4;

    u64 acc[8][2];
#pragma unroll
    for (int i = 0; i < 8; i++) { acc[i][0] = 0ull; acc[i][1] = 0ull; }

    int ar = tid >> 1, ac = (tid & 1) * 8;    // A: row ar, k-cols ac..ac+7
    int brow = tid >> 4, bc = (tid & 15) * 4; // W: k-row brow, cols bc..bc+3

    const float* aptr = &A[(size_t)(bm + ar) * K + ac];
    float4 a0 = *(const float4*)(aptr);
    float4 a1 = *(const float4*)(aptr + 4);
    float4 bv = *(const float4*)&W[(size_t)brow * N + bn + bc];

    for (int k0 = 0; k0 < K; k0 += 16) {
        __syncthreads();
        Ast2[(ac + 0) * 130 + ar] = pack2(a0.x, a0.x);
        Ast2[(ac + 1) * 130 + ar] = pack2(a0.y, a0.y);
        Ast2[(ac + 2) * 130 + ar] = pack2(a0.z, a0.z);
        Ast2[(ac + 3) * 130 + ar] = pack2(a0.w, a0.w);
        Ast2[(ac + 4) * 130 + ar] = pack2(a1.x, a1.x);
        Ast2[(ac + 5) * 130 + ar] = pack2(a1.y, a1.y);
        Ast2[(ac + 6) * 130 + ar] = pack2(a1.z, a1.z);
        Ast2[(ac + 7) * 130 + ar] = pack2(a1.w, a1.w);
        *(float4*)&Bs[brow * 68 + bc] = bv;
        __syncthreads();

        if (k0 + 16 < K) {
            a0 = *(const float4*)(aptr + k0 + 16);
            a1 = *(const float4*)(aptr + k0 + 20);
            bv = *(const float4*)&W[(size_t)(k0 + 16 + brow) * N + bn + bc];
        }

#pragma unroll
        for (int k = 0; k < 16; k++) {
            ulonglong2 qa = *(const ulonglong2*)&Ast2[k * 130 + ty * 4];
            ulonglong2 qb = *(const ulonglong2*)&Ast2[k * 130 + ty * 4 + 2];
            ulonglong2 qc = *(const ulonglong2*)&Ast2[k * 130 + 64 + ty * 4];
            ulonglong2 qd = *(const ulonglong2*)&Ast2[k * 130 + 64 + ty * 4 + 2];
            ulonglong2 b2 = *(const ulonglong2*)&Bs[k * 68 + tx * 4];
            acc[0][0] = fma2(qa.x, b2.x, acc[0][0]); acc[0][1] = fma2(qa.x, b2.y, acc[0][1]);
            acc[1][0] = fma2(qa.y, b2.x, acc[1][0]); acc[1][1] = fma2(qa.y, b2.y, acc[1][1]);
            acc[2][0] = fma2(qb.x, b2.x, acc[2][0]); acc[2][1] = fma2(qb.x, b2.y, acc[2][1]);
            acc[3][0] = fma2(qb.y, b2.x, acc[3][0]); acc[3][1] = fma2(qb.y, b2.y, acc[3][1]);
            acc[4][0] = fma2(qc.x, b2.x, acc[4][0]); acc[4][1] = fma2(qc.x, b2.y, acc[4][1]);
            acc[5][0] = fma2(qc.y, b2.x, acc[5][0]); acc[5][1] = fma2(qc.y, b2.y, acc[5][1]);
            acc[6][0] = fma2(qd.x, b2.x, acc[6][0]); acc[6][1] = fma2(qd.x, b2.y, acc[6][1]);
            acc[7][0] = fma2(qd.y, b2.x, acc[7][0]); acc[7][1] = fma2(qd.y, b2.y, acc[7][1]);
        }
    }

    float4 biasv = *(const float4*)&bias[bn + tx * 4];
#pragma unroll
    for (int i = 0; i < 8; i++) {
        int row = bm + ((i < 4) ? (ty * 4 + i) : (64 + ty * 4 + (i - 4)));
        float4 o;
        unpack2(acc[i][0], o.x, o.y);
        unpack2(acc[i][1], o.z, o.w);
        o.x += biasv.x; o.y += biasv.y; o.z += biasv.z; o.w += biasv.w;
        *(float4*)&C[(size_t)row * N + bn + tx * 4] = o;
    }
}

// ---------------------------------------------------------------------------
// od kernel
// ---------------------------------------------------------------------------
__global__ __launch_bounds__(128) void od_kernel(
    const float* __restrict__ w_od, const float* __restrict__ b_od)
{
    int bt = blockIdx.x;
    int b = bt / TT, t = bt % TT;
    const float* qrow = g_qkv + (size_t)bt * E3;

    int tid = threadIdx.x;
    int c = tid & 15, r = tid >> 4;

    float partial = 0.f;
    for (int k = r; k < EE; k += 8)
        partial = fmaf(qrow[k], w_od[k * 16 + c], partial);

    __shared__ float red[128];
    __shared__ float odv[16];
    red[tid] = partial;
    __syncthreads();
    if (tid < 16) {
        float s = 0.f;
#pragma unroll
        for (int rr = 0; rr < 8; rr++) s += red[tid + 16 * rr];
        odv[tid] = s + b_od[tid];
    }
    __syncthreads();
    if (tid < NHH) {
        int h = tid;
        float off = tanhf(odv[h]) * (float)TT;
        float dur = (float)TT / (1.f + expf(-odv[h + NHH]));
        float anchor = (float)t + off;
        float start = anchor - dur;
        float end   = anchor + dur;
        float blv = floorf(start);
        float brv = ceilf(end);
        float alv = floorf(anchor);
        float frv = anchor - alv;
        float* p = g_params + ((size_t)(b * NHH + h) * TT + t) * 6;
        p[0] = blv;
        p[1] = brv;
        p[2] = blv - start;
        p[3] = end - brv;
        p[4] = alv;
        p[5] = frv;
    }
}

// ---------------------------------------------------------------------------
// Flash deformable attention. 64q x 64j tiles, 256 threads, 4x4 per thread.
// Q and P stored as duplicated u64 pairs in smem; FFMA2-dense inner loops.
// ---------------------------------------------------------------------------
__global__ __launch_bounds__(256, 2) void attn_kernel()
{
    extern __shared__ __align__(16) float sm[];
    u64*   Qs2 = (u64*)sm;             // [64 k][66 q] dup pairs
    u64*   Ps2 = Qs2 + 64 * 66;        // [64 q][66 j] dup pairs
    float* KsT = (float*)(Ps2 + 64 * 66); // [64 k][64 j], XOR chunk swizzle
    float* Vs  = KsT + 64 * 64;        // [64 j][68 d]
    float* Pp  = Vs + 64 * 68;         // [64][8] params
    __shared__ int s_jt0, s_jt1;

    int qt = blockIdx.x;
    int bh = blockIdx.y;
    int b = bh >> 3, h = bh & 7;
    int tid = threadIdx.x;
    int tx = tid & 15, ty = tid >> 4;
    int q0 = qt * 64;

    // Q tile fill: coalesced float4 reads, duplicated u64 transposed writes
    const float* qbase = g_qkv + ((size_t)(b * TT) + q0) * E3 + h * HDD;
#pragma unroll
    for (int it = 0; it < 4; it++) {
        int idx = it * 256 + tid;
        int r = idx >> 4, c4 = idx & 15;
        float4 v = *(const float4*)&qbase[(size_t)r * E3 + c4 * 4];
        Qs2[(c4 * 4 + 0) * 66 + r] = pack2(v.x, v.x);
        Qs2[(c4 * 4 + 1) * 66 + r] = pack2(v.y, v.y);
        Qs2[(c4 * 4 + 2) * 66 + r] = pack2(v.z, v.z);
        Qs2[(c4 * 4 + 3) * 66 + r] = pack2(v.w, v.w);
    }
    // params
    if (tid < 64) {
        const float* p = g_params + ((size_t)bh * TT + q0 + tid) * 6;
#pragma unroll
        for (int c = 0; c < 6; c++) Pp[tid * 8 + c] = p[c];
        float lo = fmaxf(p[0], 0.f);
        float hi = fminf(p[1], (float)(TT - 1));
        Pp[tid * 8 + 6] = lo;
        Pp[tid * 8 + 7] = hi;
    }
    __syncthreads();
    if (tid == 0) {
        float jmin = 1e30f, jmax = -1e30f;
        int empty = 0;
        for (int r = 0; r < 64; r++) {
            float lo = Pp[r * 8 + 6], hi = Pp[r * 8 + 7];
            if (lo > hi) empty = 1;
            jmin = fminf(jmin, lo);
            jmax = fmaxf(jmax, hi);
        }
        if (empty) { s_jt0 = 0; s_jt1 = TT - 1; }
        else       { s_jt0 = ((int)jmin) & ~63; s_jt1 = (int)jmax; }
    }
    __syncthreads();

    float bl[4], br[4], wbl[4], wbr[4], al[4], fr[4];
#pragma unroll
    for (int i = 0; i < 4; i++) {
        int r = ty * 4 + i;
        bl[i] = Pp[r * 8 + 0]; br[i] = Pp[r * 8 + 1];
        wbl[i] = Pp[r * 8 + 2]; wbr[i] = Pp[r * 8 + 3];
        al[i] = Pp[r * 8 + 4]; fr[i] = Pp[r * 8 + 5];
    }

    float m[4], l[4];
    u64 acc[4][2];
#pragma unroll
    for (int i = 0; i < 4; i++) {
        m[i] = -1e30f; l[i] = 0.f; acc[i][0] = 0ull; acc[i][1] = 0ull;
    }

    const float* kbase = g_qkv + (size_t)(b * TT) * E3 + EE + h * HDD;
    const float* vbase = g_qkv + (size_t)(b * TT) * E3 + 2 * EE + h * HDD;
    int jt0 = s_jt0, jt1 = s_jt1;

    for (int jt = jt0; jt <= jt1; jt += 64) {
        __syncthreads();
        // K fill: float4 global reads, k-major XOR-swizzled scalar writes
#pragma unroll
        for (int it = 0; it < 4; it++) {
            int idx = it * 256 + tid;
            int j = idx >> 4, c4 = idx & 15;
            float4 kv = *(const float4*)&kbase[(size_t)(jt + j) * E3 + c4 * 4];
            int jg = j >> 2, jl = j & 3;
            int k0i = c4 * 4;
            KsT[(k0i + 0) * 64 + ((jg ^ ((k0i + 0) & 15)) << 2) + jl] = kv.x;
            KsT[(k0i + 1) * 64 + ((jg ^ ((k0i + 1) & 15)) << 2) + jl] = kv.y;
            KsT[(k0i + 2) * 64 + ((jg ^ ((k0i + 2) & 15)) << 2) + jl] = kv.z;
            KsT[(k0i + 3) * 64 + ((jg ^ ((k0i + 3) & 15)) << 2) + jl] = kv.w;
        }
        // V fill
#pragma unroll
        for (int it = 0; it < 4; it++) {
            int idx = it * 256 + tid;
            int r = idx >> 4, c4 = idx & 15;
            float4 v = *(const float4*)&vbase[(size_t)(jt + r) * E3 + c4 * 4];
            *(float4*)&Vs[r * 68 + c4 * 4] = v;
        }
        __syncthreads();

        // QK: 4 rows x 4 cols, FFMA2 pairs along j
        u64 s2[4][2];
#pragma unroll
        for (int i = 0; i < 4; i++) { s2[i][0] = 0ull; s2[i][1] = 0ull; }
#pragma unroll 8
        for (int k = 0; k < 64; k++) {
            ulonglong2 bq = *(const ulonglong2*)&KsT[k * 64 + ((tx ^ (k & 15)) << 2)];
            ulonglong2 qa = *(const ulonglong2*)&Qs2[k * 66 + ty * 4];
            ulonglong2 qb = *(const ulonglong2*)&Qs2[k * 66 + ty * 4 + 2];
            s2[0][0] = fma2(qa.x, bq.x, s2[0][0]); s2[0][1] = fma2(qa.x, bq.y, s2[0][1]);
            s2[1][0] = fma2(qa.y, bq.x, s2[1][0]); s2[1][1] = fma2(qa.y, bq.y, s2[1][1]);
            s2[2][0] = fma2(qb.x, bq.x, s2[2][0]); s2[2][1] = fma2(qb.x, bq.y, s2[2][1]);
            s2[3][0] = fma2(qb.y, bq.x, s2[3][0]); s2[3][1] = fma2(qb.y, bq.y, s2[3][1]);
        }

        // softmax bookkeeping
        float factor[4];
#pragma unroll
        for (int i = 0; i < 4; i++) {
            float s[4];
            unpack2(s2[i][0], s[0], s[1]);
            unpack2(s2[i][1], s[2], s[3]);
            float tmax = -1e30f;
#pragma unroll
            for (int jj = 0; jj < 4; jj++) {
                float jf = (float)(jt + tx * 4 + jj);
                float w = 1.f;
                if (jf == bl[i]) w += wbl[i];
                if (jf == br[i]) w += wbr[i];
                if (jf == al[i]) w += 1.f - fr[i];
                if (jf == al[i] + 1.f) w += fr[i];
                float sv = s[jj] * SCALE_F * w;
                if (jf < bl[i] || jf > br[i]) sv = -1e8f;
                s[jj] = sv;
                tmax = fmaxf(tmax, sv);
            }
#pragma unroll
            for (int off = 8; off >= 1; off >>= 1)
                tmax = fmaxf(tmax, __shfl_xor_sync(0xffffffffu, tmax, off));
            float mnew = fmaxf(m[i], tmax);
            factor[i] = __expf(m[i] - mnew);
            float4 pv;
            pv.x = __expf(s[0] - mnew);
            pv.y = __expf(s[1] - mnew);
            pv.z = __expf(s[2] - mnew);
            pv.w = __expf(s[3] - mnew);
            float psum = pv.x + pv.y + pv.z + pv.w;
#pragma unroll
            for (int off = 8; off >= 1; off >>= 1)
                psum += __shfl_xor_sync(0xffffffffu, psum, off);
            l[i] = l[i] * factor[i] + psum;
            m[i] = mnew;
            ulonglong2 p01; p01.x = pack2(pv.x, pv.x); p01.y = pack2(pv.y, pv.y);
            ulonglong2 p23; p23.x = pack2(pv.z, pv.z); p23.y = pack2(pv.w, pv.w);
            *(ulonglong2*)&Ps2[(ty * 4 + i) * 66 + tx * 4]     = p01;
            *(ulonglong2*)&Ps2[(ty * 4 + i) * 66 + tx * 4 + 2] = p23;
        }
        __syncthreads();

        // rescale accumulators
#pragma unroll
        for (int i = 0; i < 4; i++) {
            u64 f2 = pack2(factor[i], factor[i]);
            acc[i][0] = mul2(acc[i][0], f2);
            acc[i][1] = mul2(acc[i][1], f2);
        }
        // PV: 2-j unroll
#pragma unroll 4
        for (int j = 0; j < 64; j += 2) {
            ulonglong2 v0 = *(const ulonglong2*)&Vs[j * 68 + tx * 4];
            ulonglong2 v1 = *(const ulonglong2*)&Vs[(j + 1) * 68 + tx * 4];
#pragma unroll
            for (int i = 0; i < 4; i++) {
                ulonglong2 p = *(const ulonglong2*)&Ps2[(ty * 4 + i) * 66 + j];
                acc[i][0] = fma2(p.x, v0.x, acc[i][0]);
                acc[i][1] = fma2(p.x, v0.y, acc[i][1]);
                acc[i][0] = fma2(p.y, v1.x, acc[i][0]);
                acc[i][1] = fma2(p.y, v1.y, acc[i][1]);
            }
        }
    }

    float* ob = g_attn + ((size_t)(b * TT) + q0) * EE + h * HDD;
#pragma unroll
    for (int i = 0; i < 4; i++) {
        float inv = 1.f / l[i];
        float4 o;
        unpack2(acc[i][0], o.x, o.y);
        unpack2(acc[i][1], o.z, o.w);
        o.x *= inv; o.y *= inv; o.z *= inv; o.w *= inv;
        *(float4*)&ob[(size_t)(ty * 4 + i) * EE + tx * 4] = o;
    }
}

#define ATTN_SMEM ((64*66*8)*2 + 64*64*4 + 64*68*4 + 64*8*4)

// ---------------------------------------------------------------------------
extern "C" void kernel_launch(void* const* d_in, const int* in_sizes, int n_in,
                              void* d_out, int out_size)
{
    const float* x      = (const float*)d_in[0];
    const float* w_qkv  = (const float*)d_in[1];
    const float* b_qkv  = (const float*)d_in[2];
    const float* w_od   = (const float*)d_in[3];
    const float* b_od   = (const float*)d_in[4];
    const float* w_out  = (const float*)d_in[5];
    const float* b_out  = (const float*)d_in[6];
    float* out = (float*)d_out;

    float* qkv;  cudaGetSymbolAddress((void**)&qkv,  g_qkv);
    float* attn; cudaGetSymbolAddress((void**)&attn, g_attn);

    static int init = 0;
    if (!init) {
        init = 1;
        cudaFuncSetAttribute(attn_kernel,
                             cudaFuncAttributeMaxDynamicSharedMemorySize, ATTN_SMEM);
    }

    // 1) QKV = x @ w_qkv + b_qkv : (4096,512)@(512,1536)
    gemm_bias_kernel<<<dim3(E3 / 64, (BB * TT) / 128), 256>>>(
        x, w_qkv, b_qkv, qkv, BB * TT, E3, EE);

    // 2) window params
    od_kernel<<<BB * TT, 128>>>(w_od, b_od);

    // 3) flash deformable attention
    attn_kernel<<<dim3(TT / 64, BHH), 256, ATTN_SMEM>>>();

    // 4) out = attn @ w_out + b_out : (4096,512)@(512,512)
    gemm_bias_kernel<<<dim3(EE / 64, (BB * TT) / 128), 256>>>(
        attn, w_out, b_out, out, BB * TT, EE, EE);
}

// round 5
// speedup vs baseline: 1.9369x; 1.9369x over previous
#include <cuda_runtime.h>
#include <math.h>

#define BB 2
#define TT 2048
#define EE 512
#define NHH 8
#define HDD 64
#define BHH (BB*NHH)
#define E3 (3*EE)
#define SCALE_F 0.125f

// Scratch (no allocations allowed)
__device__ float g_qkv[(size_t)BB * TT * E3];    // 25 MB
__device__ float g_params[(size_t)BHH * TT * 6];
__device__ float g_attn[(size_t)BB * TT * EE];   // 8 MB

// ---------------------------------------------------------------------------
// tf32 helpers
// ---------------------------------------------------------------------------
__device__ __forceinline__ unsigned f2tf32(float x) {
    unsigned r; asm("cvt.rna.tf32.f32 %0, %1;" : "=r"(r) : "f"(x)); return r;
}
// 3xTF32 split: x ~= hi + lo, both tf32-representable
__device__ __forceinline__ void split_tf32(float x, unsigned& h, unsigned& l) {
    h = f2tf32(x);
    float r = x - __uint_as_float(h);
    l = f2tf32(r);
}
__device__ __forceinline__ void mma_tf32(
    float& d0, float& d1, float& d2, float& d3,
    unsigned a0, unsigned a1, unsigned a2, unsigned a3,
    unsigned b0, unsigned b1)
{
    asm("mma.sync.aligned.m16n8k8.row.col.f32.tf32.tf32.f32 "
        "{%0,%1,%2,%3}, {%4,%5,%6,%7}, {%8,%9}, {%0,%1,%2,%3};"
        : "+f"(d0), "+f"(d1), "+f"(d2), "+f"(d3)
        : "r"(a0), "r"(a1), "r"(a2), "r"(a3), "r"(b0), "r"(b1));
}

// ---------------------------------------------------------------------------
// 3xTF32 tensor-core GEMM: C[M,N] = A[M,K] @ W[K,N] + bias.
// BM=BN=128, BK=16, 256 threads = 8 warps (4 m x 2 n), warp tile m32 x n64.
// ---------------------------------------------------------------------------
__global__ __launch_bounds__(256) void gemm_bias_kernel(
    const float* __restrict__ A, const float* __restrict__ W,
    const float* __restrict__ bias, float* __restrict__ C,
    int M, int N, int K)
{
    __shared__ unsigned Ah[16 * 136];
    __shared__ unsigned Al[16 * 136];
    __shared__ unsigned Bh[16 * 136];
    __shared__ unsigned Bl[16 * 136];

    int bm = blockIdx.y * 128;
    int bn = blockIdx.x * 128;
    int tid = threadIdx.x;
    int warp = tid >> 5, lane = tid & 31;
    int wm = warp >> 1, wn = warp & 1;
    int lq = lane >> 2, lr = lane & 3;

    float acc[2][8][4];
#pragma unroll
    for (int mt = 0; mt < 2; mt++)
#pragma unroll
        for (int nt = 0; nt < 8; nt++)
#pragma unroll
            for (int c = 0; c < 4; c++) acc[mt][nt][c] = 0.f;

    int am = tid >> 1, ak = (tid & 1) * 8;
    int bk = tid >> 4, bn8 = (tid & 15) * 8;

    const float* Ap = A + (size_t)(bm + am) * K + ak;
    const float* Wp = W + (size_t)bk * N + bn + bn8;

    float4 a0v = *(const float4*)(Ap);
    float4 a1v = *(const float4*)(Ap + 4);
    float4 w0v = *(const float4*)(Wp);
    float4 w1v = *(const float4*)(Wp + 4);

    for (int k0 = 0; k0 < K; k0 += 16) {
        __syncthreads();
        {
            float av[8] = {a0v.x, a0v.y, a0v.z, a0v.w, a1v.x, a1v.y, a1v.z, a1v.w};
#pragma unroll
            for (int c = 0; c < 8; c++) {
                unsigned h, l;
                split_tf32(av[c], h, l);
                Ah[(ak + c) * 136 + am] = h;
                Al[(ak + c) * 136 + am] = l;
            }
            float wv[8] = {w0v.x, w0v.y, w0v.z, w0v.w, w1v.x, w1v.y, w1v.z, w1v.w};
            uint4 h0, h1, l0, l1;
            split_tf32(wv[0], h0.x, l0.x); split_tf32(wv[1], h0.y, l0.y);
            split_tf32(wv[2], h0.z, l0.z); split_tf32(wv[3], h0.w, l0.w);
            split_tf32(wv[4], h1.x, l1.x); split_tf32(wv[5], h1.y, l1.y);
            split_tf32(wv[6], h1.z, l1.z); split_tf32(wv[7], h1.w, l1.w);
            *(uint4*)&Bh[bk * 136 + bn8]     = h0;
            *(uint4*)&Bh[bk * 136 + bn8 + 4] = h1;
            *(uint4*)&Bl[bk * 136 + bn8]     = l0;
            *(uint4*)&Bl[bk * 136 + bn8 + 4] = l1;
        }
        __syncthreads();

        if (k0 + 16 < K) {
            a0v = *(const float4*)(Ap + k0 + 16);
            a1v = *(const float4*)(Ap + k0 + 20);
            w0v = *(const float4*)(Wp + (size_t)(k0 + 16) * N);
            w1v = *(const float4*)(Wp + (size_t)(k0 + 16) * N + 4);
        }

#pragma unroll
        for (int k8 = 0; k8 < 16; k8 += 8) {
            unsigned ah[2][4], al[2][4];
#pragma unroll
            for (int mt = 0; mt < 2; mt++) {
                int mb = wm * 32 + mt * 16 + lq;
                ah[mt][0] = Ah[(k8 + lr) * 136 + mb];
                ah[mt][1] = Ah[(k8 + lr) * 136 + mb + 8];
                ah[mt][2] = Ah[(k8 + lr + 4) * 136 + mb];
                ah[mt][3] = Ah[(k8 + lr + 4) * 136 + mb + 8];
                al[mt][0] = Al[(k8 + lr) * 136 + mb];
                al[mt][1] = Al[(k8 + lr) * 136 + mb + 8];
                al[mt][2] = Al[(k8 + lr + 4) * 136 + mb];
                al[mt][3] = Al[(k8 + lr + 4) * 136 + mb + 8];
            }
#pragma unroll
            for (int nt = 0; nt < 8; nt++) {
                int nb = wn * 64 + nt * 8 + lq;
                unsigned bh0 = Bh[(k8 + lr) * 136 + nb];
                unsigned bh1 = Bh[(k8 + lr + 4) * 136 + nb];
                unsigned bl0 = Bl[(k8 + lr) * 136 + nb];
                unsigned bl1 = Bl[(k8 + lr + 4) * 136 + nb];
#pragma unroll
                for (int mt = 0; mt < 2; mt++) {
                    mma_tf32(acc[mt][nt][0], acc[mt][nt][1], acc[mt][nt][2], acc[mt][nt][3],
                             ah[mt][0], ah[mt][1], ah[mt][2], ah[mt][3], bh0, bh1);
                    mma_tf32(acc[mt][nt][0], acc[mt][nt][1], acc[mt][nt][2], acc[mt][nt][3],
                             ah[mt][0], ah[mt][1], ah[mt][2], ah[mt][3], bl0, bl1);
                    mma_tf32(acc[mt][nt][0], acc[mt][nt][1], acc[mt][nt][2], acc[mt][nt][3],
                             al[mt][0], al[mt][1], al[mt][2], al[mt][3], bh0, bh1);
                }
            }
        }
    }

#pragma unroll
    for (int mt = 0; mt < 2; mt++) {
        int row = bm + wm * 32 + mt * 16 + lq;
#pragma unroll
        for (int nt = 0; nt < 8; nt++) {
            int col = bn + wn * 64 + nt * 8 + 2 * lr;
            float bv0 = bias[col], bv1 = bias[col + 1];
            float2 o0, o1;
            o0.x = acc[mt][nt][0] + bv0; o0.y = acc[mt][nt][1] + bv1;
            o1.x = acc[mt][nt][2] + bv0; o1.y = acc[mt][nt][3] + bv1;
            *(float2*)&C[(size_t)row * N + col] = o0;
            *(float2*)&C[(size_t)(row + 8) * N + col] = o1;
        }
    }
}

// ---------------------------------------------------------------------------
// od kernel (fp32 exact)
// ---------------------------------------------------------------------------
__global__ __launch_bounds__(128) void od_kernel(
    const float* __restrict__ w_od, const float* __restrict__ b_od)
{
    int bt = blockIdx.x;
    int b = bt / TT, t = bt % TT;
    const float* qrow = g_qkv + (size_t)bt * E3;

    int tid = threadIdx.x;
    int c = tid & 15, r = tid >> 4;

    float partial = 0.f;
    for (int k = r; k < EE; k += 8)
        partial = fmaf(qrow[k], w_od[k * 16 + c], partial);

    __shared__ float red[128];
    __shared__ float odv[16];
    red[tid] = partial;
    __syncthreads();
    if (tid < 16) {
        float s = 0.f;
#pragma unroll
        for (int rr = 0; rr < 8; rr++) s += red[tid + 16 * rr];
        odv[tid] = s + b_od[tid];
    }
    __syncthreads();
    if (tid < NHH) {
        int h = tid;
        float off = tanhf(odv[h]) * (float)TT;
        float dur = (float)TT / (1.f + expf(-odv[h + NHH]));
        float anchor = (float)t + off;
        float start = anchor - dur;
        float end   = anchor + dur;
        float blv = floorf(start);
        float brv = ceilf(end);
        float alv = floorf(anchor);
        float frv = anchor - alv;
        float* p = g_params + ((size_t)(b * NHH + h) * TT + t) * 6;
        p[0] = blv;
        p[1] = brv;
        p[2] = blv - start;
        p[3] = end - brv;
        p[4] = alv;
        p[5] = frv;
    }
}

// ---------------------------------------------------------------------------
// Tensor-core flash deformable attention.
// CTA: 128 queries, 8 warps (warp = 16 q rows), j-tiles of 64.
// QK: 1x tf32 (scores small -> abs err ~1e-4). PV: 3xTF32 (P,V split hi/lo).
// ---------------------------------------------------------------------------
#define QS_S 68
#define VS_S 72
__global__ __launch_bounds__(256) void attn_kernel()
{
    extern __shared__ unsigned smu[];
    unsigned* Qs = smu;                  // [128 q][QS_S] tf32
    unsigned* Ks = Qs + 128 * QS_S;      // [64 j][QS_S] tf32
    unsigned* Vh = Ks + 64 * QS_S;       // [64 j][VS_S] tf32 hi
    unsigned* Vl = Vh + 64 * VS_S;       // [64 j][VS_S] tf32 lo
    unsigned* Ph = Vl + 64 * VS_S;       // [128 q][QS_S] tf32 hi
    unsigned* Pl = Ph + 128 * QS_S;      // [128 q][QS_S] tf32 lo
    float*    Pp = (float*)(Pl + 128 * QS_S); // [128][8] params
    __shared__ int s_jt0, s_jt1;

    int qt = blockIdx.x;
    int bh = blockIdx.y;
    int b = bh >> 3, h = bh & 7;
    int tid = threadIdx.x;
    int warp = tid >> 5, lane = tid & 31;
    int lq = lane >> 2, lr = lane & 3;
    int q0 = qt * 128;

    // Q fill (tf32 1x)
    const float* qbase = g_qkv + ((size_t)(b * TT) + q0) * E3 + h * HDD;
#pragma unroll
    for (int it = 0; it < 8; it++) {
        int idx = it * 256 + tid;
        int r = idx >> 4, c4 = idx & 15;
        float4 v = *(const float4*)&qbase[(size_t)r * E3 + c4 * 4];
        uint4 u;
        u.x = f2tf32(v.x); u.y = f2tf32(v.y); u.z = f2tf32(v.z); u.w = f2tf32(v.w);
        *(uint4*)&Qs[r * QS_S + c4 * 4] = u;
    }
    // params
    if (tid < 128) {
        const float* p = g_params + ((size_t)bh * TT + q0 + tid) * 6;
#pragma unroll
        for (int c = 0; c < 6; c++) Pp[tid * 8 + c] = p[c];
        float lo = fmaxf(p[0], 0.f);
        float hi = fminf(p[1], (float)(TT - 1));
        Pp[tid * 8 + 6] = lo;
        Pp[tid * 8 + 7] = hi;
    }
    __syncthreads();
    if (tid == 0) {
        float jmin = 1e30f, jmax = -1e30f;
        int empty = 0;
        for (int r = 0; r < 128; r++) {
            float lo = Pp[r * 8 + 6], hi = Pp[r * 8 + 7];
            if (lo > hi) empty = 1;
            jmin = fminf(jmin, lo);
            jmax = fmaxf(jmax, hi);
        }
        if (empty) { s_jt0 = 0; s_jt1 = TT - 1; }
        else       { s_jt0 = ((int)jmin) & ~63; s_jt1 = (int)jmax; }
    }
    __syncthreads();

    int lr0 = warp * 16 + lq;
    int lr1 = lr0 + 8;
    float bl0 = Pp[lr0 * 8 + 0], br0 = Pp[lr0 * 8 + 1];
    float wbl0 = Pp[lr0 * 8 + 2], wbr0 = Pp[lr0 * 8 + 3];
    float al0 = Pp[lr0 * 8 + 4], fr0 = Pp[lr0 * 8 + 5];
    float bl1 = Pp[lr1 * 8 + 0], br1 = Pp[lr1 * 8 + 1];
    float wbl1 = Pp[lr1 * 8 + 2], wbr1 = Pp[lr1 * 8 + 3];
    float al1 = Pp[lr1 * 8 + 4], fr1 = Pp[lr1 * 8 + 5];

    // Q a-frags (persistent)
    unsigned qa[8][4];
#pragma unroll
    for (int kt = 0; kt < 8; kt++) {
        qa[kt][0] = Qs[lr0 * QS_S + kt * 8 + lr];
        qa[kt][1] = Qs[lr1 * QS_S + kt * 8 + lr];
        qa[kt][2] = Qs[lr0 * QS_S + kt * 8 + lr + 4];
        qa[kt][3] = Qs[lr1 * QS_S + kt * 8 + lr + 4];
    }

    float m0 = -1e30f, m1 = -1e30f, l0 = 0.f, l1 = 0.f;
    float o[8][4];
#pragma unroll
    for (int nt = 0; nt < 8; nt++)
#pragma unroll
        for (int c = 0; c < 4; c++) o[nt][c] = 0.f;

    const float* kbase = g_qkv + (size_t)(b * TT) * E3 + EE + h * HDD;
    const float* vbase = g_qkv + (size_t)(b * TT) * E3 + 2 * EE + h * HDD;
    int jt0 = s_jt0, jt1 = s_jt1;

    for (int jt = jt0; jt <= jt1; jt += 64) {
        __syncthreads();
        // K (1x tf32) and V (split) fill: 64 rows each, 256 threads
#pragma unroll
        for (int it = 0; it < 4; it++) {
            int idx = it * 256 + tid;
            int r = idx >> 4, c4 = idx & 15;
            float4 kv = *(const float4*)&kbase[(size_t)(jt + r) * E3 + c4 * 4];
            float4 vv = *(const float4*)&vbase[(size_t)(jt + r) * E3 + c4 * 4];
            uint4 ku;
            ku.x = f2tf32(kv.x); ku.y = f2tf32(kv.y); ku.z = f2tf32(kv.z); ku.w = f2tf32(kv.w);
            *(uint4*)&Ks[r * QS_S + c4 * 4] = ku;
            uint4 vh, vl;
            split_tf32(vv.x, vh.x, vl.x);
            split_tf32(vv.y, vh.y, vl.y);
            split_tf32(vv.z, vh.z, vl.z);
            split_tf32(vv.w, vh.w, vl.w);
            *(uint4*)&Vh[r * VS_S + c4 * 4] = vh;
            *(uint4*)&Vl[r * VS_S + c4 * 4] = vl;
        }
        __syncthreads();

        // S = Q @ K^T (m16 x n64 per warp)
        float s[8][4];
#pragma unroll
        for (int nt = 0; nt < 8; nt++)
#pragma unroll
            for (int c = 0; c < 4; c++) s[nt][c] = 0.f;
#pragma unroll
        for (int kt = 0; kt < 8; kt++) {
#pragma unroll
            for (int nt = 0; nt < 8; nt++) {
                unsigned b0 = Ks[(nt * 8 + lq) * QS_S + kt * 8 + lr];
                unsigned b1 = Ks[(nt * 8 + lq) * QS_S + kt * 8 + lr + 4];
                mma_tf32(s[nt][0], s[nt][1], s[nt][2], s[nt][3],
                         qa[kt][0], qa[kt][1], qa[kt][2], qa[kt][3], b0, b1);
            }
        }

        // weights + mask + row maxima
        float rmax0 = -1e30f, rmax1 = -1e30f;
#pragma unroll
        for (int nt = 0; nt < 8; nt++) {
            float jf0 = (float)(jt + nt * 8 + 2 * lr);
            float jf1 = jf0 + 1.f;
            {
                float w = 1.f;
                if (jf0 == bl0) w += wbl0;
                if (jf0 == br0) w += wbr0;
                if (jf0 == al0) w += 1.f - fr0;
                if (jf0 == al0 + 1.f) w += fr0;
                float sv = s[nt][0] * SCALE_F * w;
                if (jf0 < bl0 || jf0 > br0) sv = -1e8f;
                s[nt][0] = sv; rmax0 = fmaxf(rmax0, sv);
            }
            {
                float w = 1.f;
                if (jf1 == bl0) w += wbl0;
                if (jf1 == br0) w += wbr0;
                if (jf1 == al0) w += 1.f - fr0;
                if (jf1 == al0 + 1.f) w += fr0;
                float sv = s[nt][1] * SCALE_F * w;
                if (jf1 < bl0 || jf1 > br0) sv = -1e8f;
                s[nt][1] = sv; rmax0 = fmaxf(rmax0, sv);
            }
            {
                float w = 1.f;
                if (jf0 == bl1) w += wbl1;
                if (jf0 == br1) w += wbr1;
                if (jf0 == al1) w += 1.f - fr1;
                if (jf0 == al1 + 1.f) w += fr1;
                float sv = s[nt][2] * SCALE_F * w;
                if (jf0 < bl1 || jf0 > br1) sv = -1e8f;
                s[nt][2] = sv; rmax1 = fmaxf(rmax1, sv);
            }
            {
                float w = 1.f;
                if (jf1 == bl1) w += wbl1;
                if (jf1 == br1) w += wbr1;
                if (jf1 == al1) w += 1.f - fr1;
                if (jf1 == al1 + 1.f) w += fr1;
                float sv = s[nt][3] * SCALE_F * w;
                if (jf1 < bl1 || jf1 > br1) sv = -1e8f;
                s[nt][3] = sv; rmax1 = fmaxf(rmax1, sv);
            }
        }
#pragma unroll
        for (int off = 1; off <= 2; off <<= 1) {
            rmax0 = fmaxf(rmax0, __shfl_xor_sync(0xffffffffu, rmax0, off));
            rmax1 = fmaxf(rmax1, __shfl_xor_sync(0xffffffffu, rmax1, off));
        }
        float mn0 = fmaxf(m0, rmax0), mn1 = fmaxf(m1, rmax1);
        float f0 = __expf(m0 - mn0), f1 = __expf(m1 - mn1);
        float ps0 = 0.f, ps1 = 0.f;
#pragma unroll
        for (int nt = 0; nt < 8; nt++) {
            float p0 = __expf(s[nt][0] - mn0);
            float p1 = __expf(s[nt][1] - mn0);
            float p2 = __expf(s[nt][2] - mn1);
            float p3 = __expf(s[nt][3] - mn1);
            ps0 += p0 + p1; ps1 += p2 + p3;
            uint2 h0, l0v, h1, l1v;
            split_tf32(p0, h0.x, l0v.x); split_tf32(p1, h0.y, l0v.y);
            split_tf32(p2, h1.x, l1v.x); split_tf32(p3, h1.y, l1v.y);
            *(uint2*)&Ph[lr0 * QS_S + nt * 8 + 2 * lr] = h0;
            *(uint2*)&Pl[lr0 * QS_S + nt * 8 + 2 * lr] = l0v;
            *(uint2*)&Ph[lr1 * QS_S + nt * 8 + 2 * lr] = h1;
            *(uint2*)&Pl[lr1 * QS_S + nt * 8 + 2 * lr] = l1v;
        }
#pragma unroll
        for (int off = 1; off <= 2; off <<= 1) {
            ps0 += __shfl_xor_sync(0xffffffffu, ps0, off);
            ps1 += __shfl_xor_sync(0xffffffffu, ps1, off);
        }
        l0 = l0 * f0 + ps0;
        l1 = l1 * f1 + ps1;
        m0 = mn0; m1 = mn1;
        __syncwarp();

        // rescale O, then O += P @ V (3xTF32)
#pragma unroll
        for (int nt = 0; nt < 8; nt++) {
            o[nt][0] *= f0; o[nt][1] *= f0;
            o[nt][2] *= f1; o[nt][3] *= f1;
        }
#pragma unroll
        for (int kt = 0; kt < 8; kt++) {
            unsigned ph0 = Ph[lr0 * QS_S + kt * 8 + lr];
            unsigned ph1 = Ph[lr1 * QS_S + kt * 8 + lr];
            unsigned ph2 = Ph[lr0 * QS_S + kt * 8 + lr + 4];
            unsigned ph3 = Ph[lr1 * QS_S + kt * 8 + lr + 4];
            unsigned pl0 = Pl[lr0 * QS_S + kt * 8 + lr];
            unsigned pl1 = Pl[lr1 * QS_S + kt * 8 + lr];
            unsigned pl2 = Pl[lr0 * QS_S + kt * 8 + lr + 4];
            unsigned pl3 = Pl[lr1 * QS_S + kt * 8 + lr + 4];
#pragma unroll
            for (int nt = 0; nt < 8; nt++) {
                unsigned bh0 = Vh[(kt * 8 + lr) * VS_S + nt * 8 + lq];
                unsigned bh1 = Vh[(kt * 8 + lr + 4) * VS_S + nt * 8 + lq];
                unsigned bl0v = Vl[(kt * 8 + lr) * VS_S + nt * 8 + lq];
                unsigned bl1v = Vl[(kt * 8 + lr + 4) * VS_S + nt * 8 + lq];
                mma_tf32(o[nt][0], o[nt][1], o[nt][2], o[nt][3],
                         ph0, ph1, ph2, ph3, bh0, bh1);
                mma_tf32(o[nt][0], o[nt][1], o[nt][2], o[nt][3],
                         ph0, ph1, ph2, ph3, bl0v, bl1v);
                mma_tf32(o[nt][0], o[nt][1], o[nt][2], o[nt][3],
                         pl0, pl1, pl2, pl3, bh0, bh1);
            }
        }
    }

    float inv0 = 1.f / l0, inv1 = 1.f / l1;
    float* ob = g_attn + ((size_t)(b * TT) + q0) * EE + h * HDD;
#pragma unroll
    for (int nt = 0; nt < 8; nt++) {
        int col = nt * 8 + 2 * lr;
        float2 v0, v1;
        v0.x = o[nt][0] * inv0; v0.y = o[nt][1] * inv0;
        v1.x = o[nt][2] * inv1; v1.y = o[nt][3] * inv1;
        *(float2*)&ob[(size_t)lr0 * EE + col] = v0;
        *(float2*)&ob[(size_t)lr1 * EE + col] = v1;
    }
}

#define ATTN_SMEM ((128*QS_S + 64*QS_S + 2*64*VS_S + 2*128*QS_S + 128*8) * 4)

// ---------------------------------------------------------------------------
extern "C" void kernel_launch(void* const* d_in, const int* in_sizes, int n_in,
                              void* d_out, int out_size)
{
    const float* x      = (const float*)d_in[0];
    const float* w_qkv  = (const float*)d_in[1];
    const float* b_qkv  = (const float*)d_in[2];
    const float* w_od   = (const float*)d_in[3];
    const float* b_od   = (const float*)d_in[4];
    const float* w_out  = (const float*)d_in[5];
    const float* b_out  = (const float*)d_in[6];
    float* out = (float*)d_out;

    float* qkv;  cudaGetSymbolAddress((void**)&qkv,  g_qkv);
    float* attn; cudaGetSymbolAddress((void**)&attn, g_attn);

    static int init = 0;
    if (!init) {
        init = 1;
        cudaFuncSetAttribute(attn_kernel,
                             cudaFuncAttributeMaxDynamicSharedMemorySize, ATTN_SMEM);
    }

    // 1) QKV = x @ w_qkv + b_qkv : (4096,512)@(512,1536), 3xTF32
    gemm_bias_kernel<<<dim3(E3 / 128, (BB * TT) / 128), 256>>>(
        x, w_qkv, b_qkv, qkv, BB * TT, E3, EE);

    // 2) window params (fp32)
    od_kernel<<<BB * TT, 128>>>(w_od, b_od);

    // 3) tensor-core flash deformable attention
    attn_kernel<<<dim3(TT / 128, BHH), 256, ATTN_SMEM>>>();

    // 4) out = attn @ w_out + b_out : (4096,512)@(512,512), 3xTF32
    gemm_bias_kernel<<<dim3(EE / 128, (BB * TT) / 128), 256>>>(
        attn, w_out, b_out, out, BB * TT, EE, EE);
}